// round 13
// baseline (speedup 1.0000x reference)
#include <cuda_runtime.h>

#define BB 16
#define CC 256
#define HH 128
#define WW 128
#define HW (HH*WW)      // 16384
#define HW4 (HW/4)      // 4096

#define GROUP 4                 // batches per L2-resident group (67 MB)
#define NGROUP (BB/GROUP)       // 4

// Scratch (no allocations allowed)
__device__ float g_red [BB * 2 * HW];           // combined [B,2,H,W]
__device__ float g_gate[BB * HW];               // gate [B,H,W]

// ---------------------------------------------------------------------------
// Kernel 1: channel max + mean, CTA-cooperative.
// CTA = 512 threads = 32 float4-columns x 16 channel-groups (16 ch each).
// At fixed channel, one warp reads 32 consecutive float4 = 512 B (coalesced).
// Per group: GROUP * (HW4/32) = 512 CTAs.
// ---------------------------------------------------------------------------
__global__ void __launch_bounds__(512) reduce_kernel(const float* __restrict__ x,
                                                     int g) {
    __shared__ float4 s_mx[16][33];
    __shared__ float4 s_sm[16][33];

    int tid = threadIdx.x;
    int col = tid & 31;              // float4 column within tile
    int grp = tid >> 5;              // 0..15 channel group (16 ch each)

    int blk     = blockIdx.x;        // 0 .. GROUP*128-1
    int brel    = blk >> 7;
    int colBase = (blk & 127) * 32;
    int b       = g * GROUP + brel;

    const float4* xb = reinterpret_cast<const float4*>(x)
                       + ((size_t)b * CC + (size_t)grp * 16) * HW4 + colBase + col;

    float4 v0 = __ldg(xb);
    float4 mx = v0;
    float4 sm = v0;

    #pragma unroll 8
    for (int c = 1; c < 16; ++c) {
        float4 v = __ldg(xb + (size_t)c * HW4);
        mx.x = fmaxf(mx.x, v.x);  mx.y = fmaxf(mx.y, v.y);
        mx.z = fmaxf(mx.z, v.z);  mx.w = fmaxf(mx.w, v.w);
        sm.x += v.x;  sm.y += v.y;  sm.z += v.z;  sm.w += v.w;
    }

    s_mx[grp][col] = mx;
    s_sm[grp][col] = sm;
    __syncthreads();

    if (tid < 32) {
        float4 rmx = s_mx[0][tid];
        float4 rsm = s_sm[0][tid];
        #pragma unroll
        for (int s = 1; s < 16; ++s) {
            float4 m = s_mx[s][tid];
            float4 a = s_sm[s][tid];
            rmx.x = fmaxf(rmx.x, m.x);  rmx.y = fmaxf(rmx.y, m.y);
            rmx.z = fmaxf(rmx.z, m.z);  rmx.w = fmaxf(rmx.w, m.w);
            rsm.x += a.x;  rsm.y += a.y;  rsm.z += a.z;  rsm.w += a.w;
        }
        const float inv = 1.0f / (float)CC;
        float4* rout = reinterpret_cast<float4*>(g_red)
                       + (size_t)b * 2 * HW4 + colBase + tid;
        rout[0]   = rmx;
        rout[HW4] = make_float4(rsm.x * inv, rsm.y * inv, rsm.z * inv, rsm.w * inv);
    }
}

// ---------------------------------------------------------------------------
// Kernel 2: 7x7 conv over [2,H,W] + hsigmoid -> g_gate. L2-hot.
// Per group: 4 batches x 16384 outputs = 256 CTAs @ 256.
// ---------------------------------------------------------------------------
__global__ void __launch_bounds__(256) conv_kernel(const float* __restrict__ w,
                                                   const float* __restrict__ bias,
                                                   int g) {
    __shared__ float sw[98];
    __shared__ float sb;
    if (threadIdx.x < 98) sw[threadIdx.x] = w[threadIdx.x];
    if (threadIdx.x == 0) sb = bias[0];
    __syncthreads();

    int idx = blockIdx.x * blockDim.x + threadIdx.x;   // 0 .. GROUP*HW-1
    int b   = g * GROUP + (idx >> 14);
    int hw  = idx & (HW - 1);
    int h   = hw >> 7;
    int wq  = hw & (WW - 1);

    const float* mp = g_red + (size_t)b * 2 * HW;   // max plane
    const float* ap = mp + HW;                      // avg plane

    float acc = sb;
    #pragma unroll
    for (int kh = 0; kh < 7; ++kh) {
        int hh = h + kh - 3;
        if (hh < 0 || hh >= HH) continue;
        int rowoff = hh * WW;
        #pragma unroll
        for (int kw = 0; kw < 7; ++kw) {
            int ww = wq + kw - 3;
            if (ww < 0 || ww >= WW) continue;
            int off = rowoff + ww;
            acc = fmaf(sw[kh * 7 + kw],      mp[off], acc);
            acc = fmaf(sw[49 + kh * 7 + kw], ap[off], acc);
        }
    }
    g_gate[(size_t)b * HW + hw] = __saturatef((acc + 3.0f) * (1.0f / 6.0f));
}

// ---------------------------------------------------------------------------
// Kernel 3: out = x * gate. x reads should hit L2 (streamed by reduce,
// unpolluted because out stores are write-through / no-allocate via __stwt).
// __ldcs on x (evict-first, last use). 4 float4 per thread.
// Per group: 4096 CTAs @ 256.
// ---------------------------------------------------------------------------
__global__ void __launch_bounds__(256) apply_kernel(const float* __restrict__ x,
                                                    float* __restrict__ out,
                                                    int g) {
    // CTA covers 1024 consecutive float4; 4 CTAs per (b,c) plane of 4096.
    size_t base = (size_t)g * GROUP * CC * HW4
                + (size_t)blockIdx.x * 1024 + threadIdx.x;
    int hw4_0 = (int)(((size_t)blockIdx.x * 1024 + threadIdx.x) & (HW4 - 1));
    int brel  = blockIdx.x >> 10;              // / (CC*4) = /1024
    int b     = g * GROUP + brel;

    const float4* xp = reinterpret_cast<const float4*>(x) + base;
    float4*       op = reinterpret_cast<float4*>(out) + base;
    const float4* gp = reinterpret_cast<const float4*>(g_gate) + (size_t)b * HW4;

    float4 v0 = __ldcs(xp);
    float4 v1 = __ldcs(xp + 256);
    float4 v2 = __ldcs(xp + 512);
    float4 v3 = __ldcs(xp + 768);
    float4 g0 = __ldca(gp + ( hw4_0         & (HW4 - 1)));
    float4 g1 = __ldca(gp + ((hw4_0 + 256)  & (HW4 - 1)));
    float4 g2 = __ldca(gp + ((hw4_0 + 512)  & (HW4 - 1)));
    float4 g3 = __ldca(gp + ((hw4_0 + 768)  & (HW4 - 1)));

    float4 o;
    o.x = v0.x * g0.x; o.y = v0.y * g0.y; o.z = v0.z * g0.z; o.w = v0.w * g0.w;
    __stwt(op,       o);
    o.x = v1.x * g1.x; o.y = v1.y * g1.y; o.z = v1.z * g1.z; o.w = v1.w * g1.w;
    __stwt(op + 256, o);
    o.x = v2.x * g2.x; o.y = v2.y * g2.y; o.z = v2.z * g2.z; o.w = v2.w * g2.w;
    __stwt(op + 512, o);
    o.x = v3.x * g3.x; o.y = v3.y * g3.y; o.z = v3.z * g3.z; o.w = v3.w * g3.w;
    __stwt(op + 768, o);
}

// ---------------------------------------------------------------------------
extern "C" void kernel_launch(void* const* d_in, const int* in_sizes, int n_in,
                              void* d_out, int out_size) {
    const float* x      = (const float*)d_in[0];   // [16,256,128,128]
    const float* conv_w = (const float*)d_in[1];   // [1,2,7,7]
    const float* conv_b = (const float*)d_in[2];   // [1]
    float* out = (float*)d_out;

    for (int g = 0; g < NGROUP; ++g) {
        reduce_kernel<<<GROUP * (HW4 / 32),            512>>>(x, g);
        conv_kernel  <<<(GROUP * HW) / 256,            256>>>(conv_w, conv_b, g);
        apply_kernel <<<(GROUP * CC * HW4) / 1024,     256>>>(x, out, g);
    }
}